// round 1
// baseline (speedup 1.0000x reference)
#include <cuda_runtime.h>

#define BATCH 8192
#define BT 8          // batches per block, main kernel
#define BTV 64        // batches per block, value kernel

// ---- device scratch (no allocations allowed) ----
__device__ __align__(16) float g_Mh[128 * 32];
__device__ __align__(16) float g_Mo[128 * 32];
__device__ __align__(16) float g_G[384 * 96];     // [er|sh|so] -> [common_h|common_o|pre_r]
__device__ __align__(16) float g_Gb[96];
__device__ __align__(16) float g_G2[96 * 128];    // [sh2|so2|r1] -> hr
__device__ __align__(16) float g_b2[128];
__device__ __align__(16) float g_hr[BATCH * 128];

// ============================================================
// Kernel P: fold conv weights
// ============================================================
__global__ void prep_kernel(const float* __restrict__ c1_relW,
                            const float* __restrict__ c1_relb,
                            const float* __restrict__ c1_rootW,
                            const float* __restrict__ c2_relW,
                            const float* __restrict__ c2_relb,
                            const float* __restrict__ c2_rootW) {
    int tid = blockIdx.x * blockDim.x + threadIdx.x;
    int nth = gridDim.x * blockDim.x;

    for (int i = tid; i < 128 * 32; i += nth) {
        g_Mh[i] = c1_rootW[0 * 4096 + i] + c1_rootW[4 * 4096 + i] +
                  c1_rootW[6 * 4096 + i] - c1_relW[6 * 4096 + i];
        g_Mo[i] = c1_rootW[3 * 4096 + i] + c1_rootW[5 * 4096 + i] +
                  c1_rootW[7 * 4096 + i] - c1_relW[7 * 4096 + i];
    }
    // G: rows 0..127 = er, 128..255 = sh, 256..383 = so
    // cols 0..31 = common_h, 32..63 = common_o, 64..95 = pre_r
    for (int i = tid; i < 384 * 96; i += nth) {
        int k = i / 96, c = i % 96;
        int grp = c / 32, cc = c % 32;
        int seg = k / 128, kk = k % 128;
        int idx = kk * 32 + cc;
        float v;
        if (seg == 0) {          // er
            if (grp == 0)      v = c1_relW[0 * 4096 + idx];
            else if (grp == 1) v = c1_relW[3 * 4096 + idx];
            else               v = c1_rootW[1 * 4096 + idx] + c1_rootW[2 * 4096 + idx];
        } else if (seg == 1) {   // sh
            if (grp == 0)      v = c1_relW[6 * 4096 + idx];
            else if (grp == 1) v = c1_relW[5 * 4096 + idx];
            else               v = c1_relW[1 * 4096 + idx];
        } else {                 // so
            if (grp == 0)      v = c1_relW[4 * 4096 + idx];
            else if (grp == 1) v = c1_relW[7 * 4096 + idx];
            else               v = c1_relW[2 * 4096 + idx];
        }
        g_G[i] = v;
    }
    for (int c = tid; c < 96; c += nth) {
        int grp = c / 32, cc = c % 32;
        float v;
        if (grp == 0)      v = c1_relb[0 * 32 + cc] + c1_relb[4 * 32 + cc] + c1_relb[6 * 32 + cc];
        else if (grp == 1) v = c1_relb[3 * 32 + cc] + c1_relb[5 * 32 + cc] + c1_relb[7 * 32 + cc];
        else               v = c1_relb[1 * 32 + cc] + c1_relb[2 * 32 + cc];
        g_Gb[c] = v;
    }
    // G2: rows 0..31 = sh2 (c2_relW[1]), 32..63 = so2 (c2_relW[2]), 64..95 = r1 (root1+root2)
    for (int i = tid; i < 96 * 128; i += nth) {
        int k = i / 128, c = i % 128;
        float v;
        if (k < 32)      v = c2_relW[1 * 4096 + k * 128 + c];
        else if (k < 64) v = c2_relW[2 * 4096 + (k - 32) * 128 + c];
        else             v = c2_rootW[1 * 4096 + (k - 64) * 128 + c] +
                             c2_rootW[2 * 4096 + (k - 64) * 128 + c];
        g_G2[i] = v;
    }
    for (int c = tid; c < 128; c += nth)
        g_b2[c] = c2_relb[1 * 128 + c] + c2_relb[2 * 128 + c];
}

// ============================================================
// Kernel E: embeddings + both conv layers -> hr  (the heavy one)
// ============================================================
// smem layout (floats):
//   sW0h 1792 | sW0o 1792 | sW0r 1536 | sb0h/sb0o/sb0r 256 ea | sb1h/o/r 128 ea
//   sX 3120 | sH1 8192 | sE 4096 | sE2 7680 | sESS 3072 | sVEC 768
// total 33200 floats = 132800 bytes
#define MAIN_SMEM_FLOATS 33200

__global__ void __launch_bounds__(256, 1) main_kernel(
    const float* __restrict__ state,
    const float* __restrict__ wrW0, const float* __restrict__ wrb0,
    const float* __restrict__ wrW1, const float* __restrict__ wrb1,
    const float* __restrict__ whW0, const float* __restrict__ whb0,
    const float* __restrict__ whW1, const float* __restrict__ whb1,
    const float* __restrict__ woW0, const float* __restrict__ wob0,
    const float* __restrict__ woW1, const float* __restrict__ wob1) {
    extern __shared__ float sm[];
    float* sW0h = sm;
    float* sW0o = sW0h + 1792;
    float* sW0r = sW0o + 1792;
    float* sb0h = sW0r + 1536;
    float* sb0o = sb0h + 256;
    float* sb0r = sb0o + 256;
    float* sb1h = sb0r + 256;
    float* sb1o = sb1h + 128;
    float* sb1r = sb1o + 128;
    float* sX   = sb1r + 128;          // BT*390
    float* sH1  = sX + BT * 390;       // 32*256
    float* sE   = sH1 + 8192;          // 32*128
    float* sE2  = sE + 4096;           // BT*960  (per-node e@M, 30 nodes x 32)
    float* sESS = sE2 + BT * 960;      // BT*384  ([er | sh | so])
    float* sVEC = sESS + BT * 384;     // BT*96

    const int tid = threadIdx.x;
    const int b0 = blockIdx.x * BT;

    for (int i = tid; i < 1792; i += 256) { sW0h[i] = whW0[i]; sW0o[i] = woW0[i]; }
    for (int i = tid; i < 1536; i += 256) sW0r[i] = wrW0[i];
    { sb0h[tid] = whb0[tid]; sb0o[tid] = wob0[tid]; sb0r[tid] = wrb0[tid]; }
    if (tid < 128) { sb1h[tid] = whb1[tid]; sb1o[tid] = wob1[tid]; sb1r[tid] = wrb1[tid]; }
    for (int i = tid; i < BT * 390; i += 256) sX[i] = state[b0 * 390 + i];
    for (int i = tid; i < BT * 384; i += 256) sESS[i] = 0.f;
    __syncthreads();

    for (int type = 0; type < 3; ++type) {
        const int npb     = (type == 0) ? 20 : (type == 1) ? 10 : 1;
        const int nodeb   = (type == 1) ? 20 : 0;
        const int K0      = (type == 2) ? 6 : 7;
        const int featoff = (type == 2) ? 0 : 6;
        const float* sW0  = (type == 0) ? sW0h : (type == 1) ? sW0o : sW0r;
        const float* sb0  = (type == 0) ? sb0h : (type == 1) ? sb0o : sb0r;
        const float* sb1v = (type == 0) ? sb1h : (type == 1) ? sb1o : sb1r;
        const float* W1g  = (type == 0) ? whW1 : (type == 1) ? woW1 : wrW1;
        const float* Mg   = (type == 0) ? g_Mh : g_Mo;
        const int nrows   = BT * npb;
        const int sumoff  = (type == 0) ? 128 : 256;

        for (int rt = 0; rt < nrows; rt += 32) {
            const int valid = min(32, nrows - rt);

            // (a) layer1: h1 = relu(x @ W0 + b0), 32 rows x 256 cols
            {
                const int j = tid;
                float w0r[7];
                #pragma unroll
                for (int k = 0; k < 7; ++k) w0r[k] = (k < K0) ? sW0[k * 256 + j] : 0.f;
                const float bias = sb0[j];
                for (int r = 0; r < 32; ++r) {
                    int gr = rt + r; if (gr >= nrows) gr = nrows - 1;
                    const int b = gr / npb, node = nodeb + gr % npb;
                    const float* x = &sX[b * 390 + node * 13 + featoff];
                    float acc = bias;
                    #pragma unroll
                    for (int k = 0; k < 7; ++k) acc += x[k] * w0r[k];
                    sH1[r * 256 + j] = fmaxf(acc, 0.f);
                }
            }
            __syncthreads();

            // (b) layer2: e = relu(h1 @ W1 + b1), 32x128, K=256; 4x4 register blocking
            {
                const int warp = tid >> 5, lane = tid & 31;
                const int r0 = warp * 4;
                float acc[4][4];
                #pragma unroll
                for (int i = 0; i < 4; ++i)
                    #pragma unroll
                    for (int j = 0; j < 4; ++j) acc[i][j] = 0.f;
                const float* W1p = W1g + lane;
                for (int k = 0; k < 256; k += 4) {
                    float4 a[4];
                    #pragma unroll
                    for (int i = 0; i < 4; ++i)
                        a[i] = *reinterpret_cast<const float4*>(&sH1[(r0 + i) * 256 + k]);
                    #pragma unroll
                    for (int kk = 0; kk < 4; ++kk) {
                        float w[4];
                        #pragma unroll
                        for (int j = 0; j < 4; ++j) w[j] = W1p[(k + kk) * 128 + 32 * j];
                        #pragma unroll
                        for (int i = 0; i < 4; ++i) {
                            const float av = (kk == 0) ? a[i].x : (kk == 1) ? a[i].y :
                                             (kk == 2) ? a[i].z : a[i].w;
                            #pragma unroll
                            for (int j = 0; j < 4; ++j) acc[i][j] += av * w[j];
                        }
                    }
                }
                #pragma unroll
                for (int i = 0; i < 4; ++i)
                    #pragma unroll
                    for (int j = 0; j < 4; ++j) {
                        const int c = lane + 32 * j;
                        sE[(r0 + i) * 128 + c] = fmaxf(acc[i][j] + sb1v[c], 0.f);
                    }
            }
            __syncthreads();

            // (c) post-process
            if (type < 2) {
                if (tid < 128) {   // accumulate sh/so per batch
                    const int c = tid;
                    int r = 0;
                    while (r < valid) {
                        const int gr = rt + r;
                        const int b = gr / npb;
                        const int rend = min(valid, r + (npb - gr % npb));
                        float s = 0.f;
                        for (int rr = r; rr < rend; ++rr) s += sE[rr * 128 + c];
                        sESS[b * 384 + sumoff + c] += s;
                        r = rend;
                    }
                }
                {   // e2 = e @ M (128 -> 32), one float4 of cols per thread
                    const int r = tid >> 3, cq = tid & 7;
                    if (r < valid) {
                        const int gr = rt + r;
                        const int b = gr / npb, node = nodeb + gr % npb;
                        float4 a4 = make_float4(0.f, 0.f, 0.f, 0.f);
                        const float4* M4 = reinterpret_cast<const float4*>(Mg) + cq;
                        const float* Er = &sE[r * 128];
                        #pragma unroll 4
                        for (int k = 0; k < 128; ++k) {
                            const float av = Er[k];
                            const float4 w4 = M4[k * 8];
                            a4.x += av * w4.x; a4.y += av * w4.y;
                            a4.z += av * w4.z; a4.w += av * w4.w;
                        }
                        *(reinterpret_cast<float4*>(&sE2[b * 960 + node * 32]) + cq) = a4;
                    }
                }
            } else {
                for (int i = tid; i < BT * 128; i += 256) {
                    const int b = i >> 7, c = i & 127;
                    sESS[b * 384 + c] = sE[b * 128 + c];   // er
                }
            }
            __syncthreads();
        }
    }

    // (d)+(e) conv1 commons + per-node relu sums -> [sh2|so2|r1]
    {
        const int b = tid >> 5, c0 = tid & 31;
        float a0 = g_Gb[c0], a1 = g_Gb[c0 + 32], a2 = g_Gb[c0 + 64];
        const float* in = &sESS[b * 384];
        for (int k = 0; k < 384; ++k) {
            const float av = in[k];
            a0 += av * g_G[k * 96 + c0];
            a1 += av * g_G[k * 96 + c0 + 32];
            a2 += av * g_G[k * 96 + c0 + 64];
        }
        float sh2 = 0.f, so2 = 0.f;
        const float* e2b = &sE2[b * 960];
        #pragma unroll
        for (int n = 0; n < 20; ++n) sh2 += fmaxf(a0 + e2b[n * 32 + c0], 0.f);
        #pragma unroll
        for (int n = 0; n < 10; ++n) so2 += fmaxf(a1 + e2b[(20 + n) * 32 + c0], 0.f);
        sVEC[b * 96 + c0]      = sh2;
        sVEC[b * 96 + 32 + c0] = so2;
        sVEC[b * 96 + 64 + c0] = fmaxf(a2, 0.f);
    }
    __syncthreads();

    // (f) hr = relu([sh2|so2|r1] @ G2 + b2)
    {
        const int b = tid >> 5, cg = tid & 31;
        float acc[4];
        #pragma unroll
        for (int j = 0; j < 4; ++j) acc[j] = g_b2[cg + 32 * j];
        const float* in = &sVEC[b * 96];
        for (int k = 0; k < 96; ++k) {
            const float av = in[k];
            #pragma unroll
            for (int j = 0; j < 4; ++j) acc[j] += av * g_G2[k * 128 + cg + 32 * j];
        }
        #pragma unroll
        for (int j = 0; j < 4; ++j)
            g_hr[(b0 + b) * 128 + cg + 32 * j] = fmaxf(acc[j], 0.f);
    }
}

// ============================================================
// Kernel V: value MLP 128->256->128->1
// ============================================================
// smem: sHR 8192 | sP 16384 | sQ 64*129=8256 -> 32832 floats = 131328 B
#define VAL_SMEM_FLOATS 32832

__global__ void __launch_bounds__(256, 1) value_kernel(
    const float* __restrict__ vW0, const float* __restrict__ vb0,
    const float* __restrict__ vW1, const float* __restrict__ vb1,
    const float* __restrict__ vW2, const float* __restrict__ vb2,
    float* __restrict__ out) {
    extern __shared__ float sm[];
    float* sHR = sm;              // 64x128
    float* sP  = sHR + 8192;      // 64x256
    float* sQ  = sP + 16384;      // 64x129 (padded)

    const int tid = threadIdx.x;
    const int b0 = blockIdx.x * BTV;

    for (int i = tid; i < BTV * 128; i += 256) sHR[i] = g_hr[b0 * 128 + i];
    __syncthreads();

    // P = relu(HR @ vW0 + b0): 64x256, K=128; 8x8 blocking
    {
        const int warp = tid >> 5, lane = tid & 31;
        const int r0 = warp * 8;
        float acc[8][8];
        #pragma unroll
        for (int i = 0; i < 8; ++i)
            #pragma unroll
            for (int j = 0; j < 8; ++j) acc[i][j] = 0.f;
        const float* Wp = vW0 + lane;
        for (int k = 0; k < 128; ++k) {
            float a[8], w[8];
            #pragma unroll
            for (int i = 0; i < 8; ++i) a[i] = sHR[(r0 + i) * 128 + k];
            #pragma unroll
            for (int j = 0; j < 8; ++j) w[j] = Wp[k * 256 + 32 * j];
            #pragma unroll
            for (int i = 0; i < 8; ++i)
                #pragma unroll
                for (int j = 0; j < 8; ++j) acc[i][j] += a[i] * w[j];
        }
        #pragma unroll
        for (int i = 0; i < 8; ++i)
            #pragma unroll
            for (int j = 0; j < 8; ++j) {
                const int c = lane + 32 * j;
                sP[(r0 + i) * 256 + c] = fmaxf(acc[i][j] + vb0[c], 0.f);
            }
    }
    __syncthreads();

    // Q = relu(P @ vW1 + b1): 64x128, K=256; 8x4 blocking
    {
        const int warp = tid >> 5, lane = tid & 31;
        const int r0 = warp * 8;
        float acc[8][4];
        #pragma unroll
        for (int i = 0; i < 8; ++i)
            #pragma unroll
            for (int j = 0; j < 4; ++j) acc[i][j] = 0.f;
        const float* Wp = vW1 + lane;
        for (int k = 0; k < 256; ++k) {
            float a[8], w[4];
            #pragma unroll
            for (int i = 0; i < 8; ++i) a[i] = sP[(r0 + i) * 256 + k];
            #pragma unroll
            for (int j = 0; j < 4; ++j) w[j] = Wp[k * 128 + 32 * j];
            #pragma unroll
            for (int i = 0; i < 8; ++i)
                #pragma unroll
                for (int j = 0; j < 4; ++j) acc[i][j] += a[i] * w[j];
        }
        #pragma unroll
        for (int i = 0; i < 8; ++i)
            #pragma unroll
            for (int j = 0; j < 4; ++j) {
                const int c = lane + 32 * j;
                sQ[(r0 + i) * 129 + c] = fmaxf(acc[i][j] + vb1[c], 0.f);
            }
    }
    __syncthreads();

    if (tid < BTV) {
        float acc = vb2[0];
        const float* q = &sQ[tid * 129];
        #pragma unroll 4
        for (int k = 0; k < 128; ++k) acc += q[k] * vW2[k];
        out[b0 + tid] = acc;
    }
}

// ============================================================
extern "C" void kernel_launch(void* const* d_in, const int* in_sizes, int n_in,
                              void* d_out, int out_size) {
    const float* state   = (const float*)d_in[0];
    const float* wrW0    = (const float*)d_in[2];
    const float* wrb0    = (const float*)d_in[3];
    const float* wrW1    = (const float*)d_in[4];
    const float* wrb1    = (const float*)d_in[5];
    const float* whW0    = (const float*)d_in[6];
    const float* whb0    = (const float*)d_in[7];
    const float* whW1    = (const float*)d_in[8];
    const float* whb1    = (const float*)d_in[9];
    const float* woW0    = (const float*)d_in[10];
    const float* wob0    = (const float*)d_in[11];
    const float* woW1    = (const float*)d_in[12];
    const float* wob1    = (const float*)d_in[13];
    const float* c1_relW = (const float*)d_in[14];
    const float* c1_relb = (const float*)d_in[15];
    const float* c1_rootW= (const float*)d_in[16];
    const float* c2_relW = (const float*)d_in[17];
    const float* c2_relb = (const float*)d_in[18];
    const float* c2_rootW= (const float*)d_in[19];
    const float* vW0     = (const float*)d_in[20];
    const float* vb0     = (const float*)d_in[21];
    const float* vW1     = (const float*)d_in[22];
    const float* vb1     = (const float*)d_in[23];
    const float* vW2     = (const float*)d_in[24];
    const float* vb2     = (const float*)d_in[25];
    float* out = (float*)d_out;

    cudaFuncSetAttribute(main_kernel, cudaFuncAttributeMaxDynamicSharedMemorySize,
                         MAIN_SMEM_FLOATS * 4);
    cudaFuncSetAttribute(value_kernel, cudaFuncAttributeMaxDynamicSharedMemorySize,
                         VAL_SMEM_FLOATS * 4);

    prep_kernel<<<64, 256>>>(c1_relW, c1_relb, c1_rootW, c2_relW, c2_relb, c2_rootW);

    main_kernel<<<BATCH / BT, 256, MAIN_SMEM_FLOATS * 4>>>(
        state, wrW0, wrb0, wrW1, wrb1, whW0, whb0, whW1, whb1,
        woW0, wob0, woW1, wob1);

    value_kernel<<<BATCH / BTV, 256, VAL_SMEM_FLOATS * 4>>>(
        vW0, vb0, vW1, vb1, vW2, vb2, out);
}